// round 15
// baseline (speedup 1.0000x reference)
#include <cuda_runtime.h>
#include <cuda_fp16.h>
#include <math.h>
#include <stdint.h>

#define BB 2
#define TT 1024
#define DIM 1024
#define DEPTH 2
#define DSTATE 128
#define HEADDIM 64
#define NHEADS 32
#define DINNER 2048
#define CONVCH 2304
#define DINPROJ 4384
#define NPAD_IN 4480          // 35*128 padded in_proj rows
#define VOCAB 256
#define BT (BB*TT)
#define NSEG 4
#define TSEG (TT/NSEG)        // 256

// ---------------- scratch (device globals; no allocations allowed) ----------
__device__ float g_h  [BT * DIM];
__device__ float g_zx [BT * DINPROJ];
__device__ float g_xbc[BT * CONVCH];       // conv+silu output
__device__ float g_yp [BT * DINNER];       // scan output (full n-reduced)
__device__ float g_acum [BB * NHEADS * TT];
__device__ float g_send [BB * NHEADS * NSEG * 64 * DSTATE];
__device__ float g_sstart[BB * NHEADS * (NSEG-1) * 64 * DSTATE];
// fragment-packed fp16 operands
__device__ uint4 g_win_pk [DEPTH * (NPAD_IN/8) * (DIM/32)    * 32];
__device__ uint4 g_wout_pk[DEPTH * (DIM/8)     * (DINNER/32) * 32];
__device__ uint4 g_emb_pk [(VOCAB/8) * (DIM/32) * 32];
__device__ uint4 g_h_pk   [(BT/16) * (DIM/16)    * 32];
__device__ uint4 g_y_pk   [(BT/16) * (DINNER/16) * 32];

// ---------------- helpers ----------------
__device__ __forceinline__ uint32_t h2u(float lo, float hi) {
    __half2 h = __floats2half2_rn(lo, hi);
    return *(uint32_t*)&h;
}
__device__ __forceinline__ void pk_store(uint32_t* __restrict__ P, int K,
                                         int m, int c, float lo, float hi) {
    int word = (((m >> 4) * (K >> 4) + (c >> 4)) << 5) + ((m & 7) << 2) +
               ((c >> 1) & 3);
    P[(word << 2) + ((m >> 3) & 1) + (((c >> 3) & 1) << 1)] = h2u(lo, hi);
}
__device__ __forceinline__ void mma_f16(float* c,
                                        uint32_t a0, uint32_t a1,
                                        uint32_t a2, uint32_t a3,
                                        uint32_t b0, uint32_t b1) {
    asm volatile(
        "mma.sync.aligned.m16n8k16.row.col.f32.f16.f16.f32 "
        "{%0,%1,%2,%3}, {%4,%5,%6,%7}, {%8,%9}, {%0,%1,%2,%3};"
        : "+f"(c[0]), "+f"(c[1]), "+f"(c[2]), "+f"(c[3])
        : "r"(a0), "r"(a1), "r"(a2), "r"(a3), "r"(b0), "r"(b1));
}
__device__ __forceinline__ void cpa16(uint32_t dst, const void* src) {
    asm volatile("cp.async.cg.shared.global [%0], [%1], 16;"
                 :: "r"(dst), "l"(src));
}
__device__ __forceinline__ void cpa4(uint32_t dst, const void* src) {
    asm volatile("cp.async.ca.shared.global [%0], [%1], 4;"
                 :: "r"(dst), "l"(src));
}
__device__ __forceinline__ uint32_t smem_u32(const void* p) {
    uint32_t a;
    asm("{ .reg .u64 t; cvta.to.shared.u64 t, %1; cvt.u32.u64 %0, t; }"
        : "=r"(a) : "l"(p));
    return a;
}

// ---------------- weight pack: fp32 [Nsrc,K] -> fp16 fragment order --------
__global__ void pack_b(const float* __restrict__ B, uint4* __restrict__ P,
                       int K, int Nsrc) {
    int idx  = blockIdx.x * 256 + threadIdx.x;
    int lane = idx & 31;
    int t2   = idx >> 5;
    int kpn  = K >> 5;
    int kp   = t2 % kpn;
    int nt   = t2 / kpn;
    int g = lane >> 2, q = lane & 3;
    int n  = nt * 8 + g;
    uint4 w = make_uint4(0u, 0u, 0u, 0u);
    if (n < Nsrc) {
        const float* r = B + (size_t)n * K + kp * 32 + 2 * q;
        float2 f0 = *(const float2*)r;
        float2 f1 = *(const float2*)(r + 8);
        float2 f2 = *(const float2*)(r + 16);
        float2 f3 = *(const float2*)(r + 24);
        w = make_uint4(h2u(f0.x, f0.y), h2u(f1.x, f1.y),
                       h2u(f2.x, f2.y), h2u(f3.x, f3.y));
    }
    P[idx] = w;
}

// ---------------- embedding gather (fp32 + packed fp16) ----------------
__global__ void embed_kernel(const int* __restrict__ x,
                             const float* __restrict__ embed,
                             float* __restrict__ h,
                             uint32_t* __restrict__ hpk) {
    int bt  = blockIdx.x;
    int tok = x[bt];
    const float4* src = (const float4*)(embed + (size_t)tok * DIM);
    float4 v = src[threadIdx.x];
    ((float4*)(h + (size_t)bt * DIM))[threadIdx.x] = v;
    int c0 = threadIdx.x * 4;
    pk_store(hpk, DIM, bt, c0,     v.x, v.y);
    pk_store(hpk, DIM, bt, c0 + 2, v.z, v.w);
}

// ---------------- templated packed fp16 GEMM (R12-proven) ------------------
template<int BM, int BN, int WM, int WN>
__global__ void __launch_bounds__(256, 2)
gemm_t(int N, int K,
       const uint4* __restrict__ Apk,
       const uint4* __restrict__ Bpk,
       const float* __restrict__ Res,
       float* __restrict__ C,
       uint32_t* __restrict__ Cpk) {
    constexpr int MT  = BM / 16 / WM;
    constexpr int NT  = BN / 8 / WN;
    constexpr int AW  = BM * 8;
    constexpr int BW  = BN * 8;
    constexpr int STW = AW + BW;
    constexpr int NA  = AW / 256;
    constexpr int NB  = BW / 256;
    extern __shared__ uint4 sm4[];
    const uint32_t sbase = smem_u32(sm4);

    const int tid    = threadIdx.x;
    const int lane   = tid & 31;
    const int wid    = tid >> 5;
    const int warp_m = wid / WN;
    const int warp_n = wid % WN;
    const int g      = lane >> 2;
    const int q      = lane & 3;
    const int row0   = blockIdx.y * BM;
    const int col0   = blockIdx.x * BN;
    const int ktn16  = K >> 4;
    const int kpn    = K >> 5;
    const int ktn    = K >> 6;

    const uint4* asrc[NA]; uint32_t adst[NA];
    const uint4* bsrc[NB]; uint32_t bdst[NB];
#pragma unroll
    for (int i = 0; i < NA; i++) {
        int ca = tid + 256 * i, la = ca & 31, r = ca >> 5;
        int ksl = r & 3, mti = r >> 2;
        asrc[i] = Apk + ((size_t)(row0 / 16 + mti) * ktn16 + ksl) * 32 + la;
        adst[i] = ca;
    }
#pragma unroll
    for (int i = 0; i < NB; i++) {
        int cb = tid + 256 * i, la = cb & 31, r = cb >> 5;
        int kpl = r & 1, nti = r >> 1;
        bsrc[i] = Bpk + ((size_t)(col0 / 8 + nti) * kpn + kpl) * 32 + la;
        bdst[i] = AW + cb;
    }

    float acc[MT][NT][4];
#pragma unroll
    for (int i = 0; i < MT; i++)
#pragma unroll
        for (int j = 0; j < NT; j++)
#pragma unroll
            for (int r = 0; r < 4; r++) acc[i][j][r] = 0.f;

#pragma unroll
    for (int p = 0; p < 2; p++) {
        uint32_t sb = sbase + p * STW * 16;
#pragma unroll
        for (int i = 0; i < NA; i++) cpa16(sb + adst[i] * 16, asrc[i] + p * 128);
#pragma unroll
        for (int i = 0; i < NB; i++) cpa16(sb + bdst[i] * 16, bsrc[i] + p * 64);
        asm volatile("cp.async.commit_group;");
    }

    for (int kt = 0; kt < ktn; kt++) {
        asm volatile("cp.async.wait_group 1;");
        __syncthreads();

        if (kt + 2 < ktn) {
            uint32_t sb = sbase + ((kt + 2) % 3) * STW * 16;
            size_t ao = (size_t)(kt + 2) * 128;
            size_t bo = (size_t)(kt + 2) * 64;
#pragma unroll
            for (int i = 0; i < NA; i++) cpa16(sb + adst[i] * 16, asrc[i] + ao);
#pragma unroll
            for (int i = 0; i < NB; i++) cpa16(sb + bdst[i] * 16, bsrc[i] + bo);
        }
        asm volatile("cp.async.commit_group;");

        const uint4* Ab = sm4 + (kt % 3) * STW;
        const uint4* Bb = Ab + AW;
#pragma unroll
        for (int kp = 0; kp < 2; kp++) {
            uint4 bw[NT];
#pragma unroll
            for (int nt = 0; nt < NT; nt++)
                bw[nt] = Bb[((warp_n * NT + nt) * 2 + kp) * 32 + lane];
#pragma unroll
            for (int hl = 0; hl < 2; hl++) {
                const int ks = kp * 2 + hl;
                uint4 af[MT];
#pragma unroll
                for (int mt = 0; mt < MT; mt++)
                    af[mt] = Ab[((warp_m * MT + mt) * 4 + ks) * 32 + lane];
#pragma unroll
                for (int mt = 0; mt < MT; mt++)
#pragma unroll
                    for (int nt = 0; nt < NT; nt++) {
                        uint32_t b0 = hl ? bw[nt].z : bw[nt].x;
                        uint32_t b1 = hl ? bw[nt].w : bw[nt].y;
                        mma_f16(acc[mt][nt], af[mt].x, af[mt].y, af[mt].z,
                                af[mt].w, b0, b1);
                    }
            }
        }
    }

#pragma unroll
    for (int mt = 0; mt < MT; mt++) {
        int r_lo = row0 + (warp_m * MT + mt) * 16 + g;
#pragma unroll
        for (int nt = 0; nt < NT; nt++) {
            int c = col0 + (warp_n * NT + nt) * 8 + q * 2;
            if (c < N) {
                float2 v0 = make_float2(acc[mt][nt][0], acc[mt][nt][1]);
                float2 v1 = make_float2(acc[mt][nt][2], acc[mt][nt][3]);
                size_t o0 = (size_t)r_lo * N + c;
                size_t o1 = (size_t)(r_lo + 8) * N + c;
                if (Res) {
                    float2 r0v = *(const float2*)(Res + o0);
                    float2 r1v = *(const float2*)(Res + o1);
                    v0.x += r0v.x; v0.y += r0v.y;
                    v1.x += r1v.x; v1.y += r1v.y;
                }
                *(float2*)(C + o0) = v0;
                *(float2*)(C + o1) = v1;
                if (Cpk) {
                    pk_store(Cpk, N, r_lo,     c, v0.x, v0.y);
                    pk_store(Cpk, N, r_lo + 8, c, v1.x, v1.y);
                }
            }
        }
    }
}

// ---------------- causal conv (K=4) + SiLU, channel-per-thread -------------
__global__ void __launch_bounds__(256)
conv_ch_kernel(const float* __restrict__ zx,
               const float* __restrict__ cw,
               const float* __restrict__ cb,
               float* __restrict__ xbc) {
    const int ch = blockIdx.x * 256 + threadIdx.x;
    const int t0 = blockIdx.y * 64;
    const int b  = blockIdx.z;
    float4 w = *(const float4*)(cw + ch * 4);
    float bias = cb[ch];
    const float* src = zx + (size_t)(b * TT) * DINPROJ + DINNER + ch;
    float* dst = xbc + (size_t)(b * TT) * CONVCH + ch;
    float x0 = 0.f, x1 = 0.f, x2 = 0.f;
    if (t0 >= 3) {
        x0 = src[(size_t)(t0 - 3) * DINPROJ];
        x1 = src[(size_t)(t0 - 2) * DINPROJ];
        x2 = src[(size_t)(t0 - 1) * DINPROJ];
    }
#pragma unroll 4
    for (int t = t0; t < t0 + 64; t++) {
        float x3 = src[(size_t)t * DINPROJ];
        float acc = fmaf(x0, w.x, fmaf(x1, w.y, fmaf(x2, w.z,
                         fmaf(x3, w.w, bias))));
        acc = acc / (1.f + expf(-acc));
        dst[(size_t)t * CONVCH] = acc;
        x0 = x1; x1 = x2; x2 = x3;
    }
}

// ---------------- segmented SSM scan pass 1 (full DSTATE per CTA) ----------
// CTA per (seg, h, b) => 256 CTAs x 512 threads. Thread = (p in 64, nq in 8),
// owns 16 states covering all 128 n. lane = pl*8+nq, 3-shfl full n-reduce.
#define SCH 16
__global__ void __launch_bounds__(512)
scan_seg_kernel(const float* __restrict__ xbc,
                const float* __restrict__ zx,
                const float* __restrict__ dtb,
                const float* __restrict__ alog,
                const float* __restrict__ Dw,
                float* __restrict__ yp,
                float* __restrict__ acum,
                float* __restrict__ send) {
    __shared__ float Xs [2][SCH][64];
    __shared__ float Bss[2][SCH][DSTATE];
    __shared__ float Css[2][SCH][DSTATE];
    __shared__ float DTraw[2][SCH];
    __shared__ float As[SCH], Dts[SCH];

    const int tid  = threadIdx.x;
    const int seg  = blockIdx.x;
    const int h    = blockIdx.y;
    const int b    = blockIdx.z;
    const int lane = tid & 31;
    const int wid  = tid >> 5;
    const int pl   = lane >> 3;       // 0..3
    const int nq   = lane & 7;        // 0..7
    const int p    = wid * 4 + pl;    // 0..63

    const int xoff = h * 64;
    const int boff = DINNER;
    const int coff = DINNER + DSTATE;

    const uint32_t xs_s = smem_u32(&Xs[0][0][0]);
    const uint32_t bs_s = smem_u32(&Bss[0][0][0]);
    const uint32_t cs_s = smem_u32(&Css[0][0][0]);
    const uint32_t dt_s = smem_u32(&DTraw[0][0]);

    float s[16];
#pragma unroll
    for (int i = 0; i < 16; i++) s[i] = 0.f;
    const float dtbv = dtb[h];
    const float aexp = expf(alog[h]);
    const float Dh   = Dw[h];
    const float* xrow = xbc + (size_t)b * TT * CONVCH;
    const float* zrow = zx + (size_t)b * TT * DINPROJ;
    float* yout = yp + (size_t)b * TT * DINNER + h * 64;
    float* acrow = acum + (size_t)(b * NHEADS + h) * TT;
    float carry = 1.f;

    // stage one chunk: 1280 float4 = X 256 + B 512 + C 512 (natural order)
    auto stage = [&](int t0, int buf) {
#pragma unroll
        for (int k = 0; k < 3; k++) {
            int j = tid + 512 * k;
            if (j < 1280) {
                int tt, q4;
                uint32_t dst;
                int choff;
                if (j < 256) {
                    tt = j >> 4; q4 = j & 15;
                    choff = xoff + q4 * 4;
                    dst = xs_s + (buf * SCH * 64 + tt * 64 + q4 * 4) * 4;
                } else if (j < 768) {
                    int jj = j - 256; tt = jj >> 5; q4 = jj & 31;
                    choff = boff + q4 * 4;
                    dst = bs_s + (buf * SCH * DSTATE + tt * DSTATE + q4 * 4) * 4;
                } else {
                    int jj = j - 768; tt = jj >> 5; q4 = jj & 31;
                    choff = coff + q4 * 4;
                    dst = cs_s + (buf * SCH * DSTATE + tt * DSTATE + q4 * 4) * 4;
                }
                cpa16(dst, xrow + (size_t)(t0 + tt) * CONVCH + choff);
            }
        }
        if (tid < SCH)
            cpa4(dt_s + (buf * SCH + tid) * 4,
                 zrow + (size_t)(t0 + tid) * DINPROJ + (DINNER + CONVCH) + h);
    };

    const int tstart = seg * TSEG;
    stage(tstart, 0);
    asm volatile("cp.async.commit_group;");

    const int nchunks = TSEG / SCH;
    for (int c = 0; c < nchunks; c++) {
        const int buf = c & 1;
        const int t0 = tstart + c * SCH;
        if (c + 1 < nchunks) stage(t0 + SCH, buf ^ 1);
        asm volatile("cp.async.commit_group;");
        asm volatile("cp.async.wait_group 1;");
        __syncthreads();

        if (tid < SCH) {
            float v = DTraw[buf][tid] + dtbv;
            float d = (v > 20.f) ? v : log1pf(expf(v));
            Dts[tid] = d;
            As[tid]  = expf(-aexp * d);
        }
        __syncthreads();

        if (tid == 0) {
            float cc = carry;
#pragma unroll
            for (int tt = 0; tt < SCH; tt++) {
                cc *= As[tt];
                acrow[t0 + tt] = cc;
            }
            carry = cc;
        }

#pragma unroll
        for (int tt = 0; tt < SCH; tt++) {
            const float da   = As[tt];
            const float xv   = Xs[buf][tt][p];
            const float coef = Dts[tt] * xv;
            const float4* B4 = (const float4*)&Bss[buf][tt][0];
            const float4* C4 = (const float4*)&Css[buf][tt][0];
            float part = 0.f;
#pragma unroll
            for (int k = 0; k < 4; k++) {
                float4 bv = B4[nq * 4 + k];
                float4 cv = C4[nq * 4 + k];
                float* sp = s + k * 4;
                sp[0] = fmaf(da, sp[0], coef * bv.x);
                sp[1] = fmaf(da, sp[1], coef * bv.y);
                sp[2] = fmaf(da, sp[2], coef * bv.z);
                sp[3] = fmaf(da, sp[3], coef * bv.w);
                part = fmaf(sp[0], cv.x, part);
                part = fmaf(sp[1], cv.y, part);
                part = fmaf(sp[2], cv.z, part);
                part = fmaf(sp[3], cv.w, part);
            }
            part += __shfl_xor_sync(0xFFFFFFFFu, part, 1);
            part += __shfl_xor_sync(0xFFFFFFFFu, part, 2);
            part += __shfl_xor_sync(0xFFFFFFFFu, part, 4);
            if (nq == 0)
                yout[(size_t)(t0 + tt) * DINNER + p] = fmaf(Dh, xv, part);
        }
        __syncthreads();
    }

    // ---- write local end state (natural n order) ----
#pragma unroll
    for (int k = 0; k < 4; k++)
#pragma unroll
        for (int j = 0; j < 4; j++)
            send[((size_t)((b * NHEADS + h) * NSEG + seg) * 64 + p) * DSTATE +
                 nq * 16 + k * 4 + j] = s[k * 4 + j];
}

// ---------------- pass 2: propagate segment init states --------------------
__global__ void propagate_kernel(const float* __restrict__ send,
                                 const float* __restrict__ acum,
                                 float* __restrict__ sstart) {
    const int h = blockIdx.x, b = blockIdx.y;
    const size_t base = (size_t)(b * NHEADS + h);
    const float* se = send + base * NSEG * 64 * DSTATE;
    float* ss = sstart + base * (NSEG - 1) * 64 * DSTATE;
    const float* ac = acum + base * TT;
    const float a1 = ac[2 * TSEG - 1];
    const float a2 = ac[3 * TSEG - 1];
    const int SEGSZ = 64 * DSTATE;
    for (int e = threadIdx.x; e < SEGSZ; e += 256) {
        float s = se[e];
        ss[e] = s;
        s = a1 * s + se[SEGSZ + e];
        ss[SEGSZ + e] = s;
        s = a2 * s + se[2 * SEGSZ + e];
        ss[2 * SEGSZ + e] = s;
    }
}

// ---------------- pass 3: correction y += A_cum * (C . S_start) ------------
__global__ void __launch_bounds__(256)
correct_kernel(const float* __restrict__ sstart,
               const float* __restrict__ acum,
               const float* __restrict__ xbc,
               float* __restrict__ yp) {
    extern __shared__ float psm[];
    float* Ssm = psm;                // [n][p] : DSTATE x 64
    float* Csm = psm + DSTATE * 64;  // [tt][n] : 64 x DSTATE
    const int sg  = blockIdx.x;
    const int seg = sg + 1;
    const int h   = blockIdx.y;
    const int b   = blockIdx.z;

    const float* S = sstart +
        ((size_t)(b * NHEADS + h) * (NSEG - 1) + sg) * 64 * DSTATE;
    for (int e = threadIdx.x; e < 64 * DSTATE; e += 256) {
        int p = e >> 7, n = e & 127;
        Ssm[n * 64 + p] = S[e];
    }

    const int p  = threadIdx.x & 63;
    const int tg = threadIdx.x >> 6;
    const float* ac = acum + (size_t)(b * NHEADS + h) * TT + seg * TSEG;

    for (int blk = 0; blk < 4; blk++) {
        __syncthreads();
        for (int e = threadIdx.x; e < 64 * DSTATE / 4; e += 256) {
            int tt = e >> 5, n4 = e & 31;
            ((float4*)(Csm + tt * DSTATE))[n4] =
                ((const float4*)(xbc +
                    (size_t)(b * TT + seg * TSEG + blk * 64 + tt) * CONVCH +
                    DINNER + DSTATE))[n4];
        }
        __syncthreads();
#pragma unroll 4
        for (int i = 0; i < 16; i++) {
            int tl = i * 4 + tg;
            int t  = seg * TSEG + blk * 64 + tl;
            float a = ac[blk * 64 + tl];
            const float4* Cr = (const float4*)(Csm + tl * DSTATE);
            float dot = 0.f;
#pragma unroll
            for (int n4 = 0; n4 < 32; n4++) {
                float4 cv = Cr[n4];
                dot = fmaf(cv.x, Ssm[(n4 * 4 + 0) * 64 + p], dot);
                dot = fmaf(cv.y, Ssm[(n4 * 4 + 1) * 64 + p], dot);
                dot = fmaf(cv.z, Ssm[(n4 * 4 + 2) * 64 + p], dot);
                dot = fmaf(cv.w, Ssm[(n4 * 4 + 3) * 64 + p], dot);
            }
            float* yptr = yp + (size_t)(b * TT + t) * DINNER + h * 64 + p;
            *yptr += a * dot;
        }
    }
}

// ---------------- fused gate + RMSNorm + packed write ----------------------
__global__ void __launch_bounds__(256)
rmsgate_kernel(const float* __restrict__ yp,
               const float* __restrict__ zx,
               const float* __restrict__ w,
               uint32_t* __restrict__ ypk) {
    __shared__ float vc[DINNER];
    __shared__ float sh[9];
    const int bt = blockIdx.x;
    const float* r0 = yp + (size_t)bt * DINNER;
    const float* zr = zx + (size_t)bt * DINPROJ;

    float ss = 0.f;
    for (int i = threadIdx.x * 2; i < DINNER; i += 512) {
        float2 a0 = *(const float2*)(r0 + i);
        float2 z2 = *(const float2*)(zr + i);
        float v0 = a0.x * (z2.x / (1.f + expf(-z2.x)));
        float v1 = a0.y * (z2.y / (1.f + expf(-z2.y)));
        vc[i] = v0; vc[i + 1] = v1;
        ss = fmaf(v0, v0, fmaf(v1, v1, ss));
    }
#pragma unroll
    for (int o = 16; o; o >>= 1) ss += __shfl_xor_sync(0xFFFFFFFFu, ss, o);
    int wd = threadIdx.x >> 5, lane = threadIdx.x & 31;
    if (lane == 0) sh[wd] = ss;
    __syncthreads();
    if (wd == 0) {
        float v = (lane < 8) ? sh[lane] : 0.f;
#pragma unroll
        for (int o = 16; o; o >>= 1) v += __shfl_xor_sync(0xFFFFFFFFu, v, o);
        if (lane == 0) sh[8] = rsqrtf(v / DINNER + 1e-5f);
    }
    __syncthreads();
    float sc = sh[8];
    for (int i = threadIdx.x * 2; i < DINNER; i += 512) {
        float o0 = vc[i] * sc * w[i];
        float o1 = vc[i + 1] * sc * w[i + 1];
        pk_store(ypk, DINNER, bt, i, o0, o1);
    }
}

// ---------------- final RMSNorm (+ packed write) ----------------
__global__ void rmsnorm_kernel(float* __restrict__ data,
                               const float* __restrict__ w, int n,
                               uint32_t* __restrict__ pk) {
    float* r = data + (size_t)blockIdx.x * n;
    float ss = 0.f;
    for (int i = threadIdx.x; i < n; i += blockDim.x) {
        float v = r[i];
        ss = fmaf(v, v, ss);
    }
#pragma unroll
    for (int o = 16; o; o >>= 1) ss += __shfl_xor_sync(0xFFFFFFFFu, ss, o);
    __shared__ float sh[9];
    int wd = threadIdx.x >> 5, lane = threadIdx.x & 31;
    if (lane == 0) sh[wd] = ss;
    __syncthreads();
    if (wd == 0) {
        float v = (lane < 8) ? sh[lane] : 0.f;
#pragma unroll
        for (int o = 16; o; o >>= 1) v += __shfl_xor_sync(0xFFFFFFFFu, v, o);
        if (lane == 0) sh[8] = rsqrtf(v / n + 1e-5f);
    }
    __syncthreads();
    float sc = sh[8];
    for (int i = threadIdx.x * 2; i < n; i += 2 * blockDim.x) {
        float o0 = r[i] * sc * w[i];
        float o1 = r[i + 1] * sc * w[i + 1];
        r[i] = o0; r[i + 1] = o1;
        pk_store(pk, n, blockIdx.x, i, o0, o1);
    }
}

// ---------------- launcher ----------------
extern "C" void kernel_launch(void* const* d_in, const int* in_sizes, int n_in,
                              void* d_out, int out_size) {
    const int*   x            = (const int*)  d_in[0];
    const float* embed        = (const float*)d_in[1];
    const float* in_proj_w    = (const float*)d_in[2];
    const float* conv_w       = (const float*)d_in[3];
    const float* conv_b       = (const float*)d_in[4];
    const float* dt_bias      = (const float*)d_in[5];
    const float* A_log        = (const float*)d_in[6];
    const float* Dw           = (const float*)d_in[7];
    const float* gnorm_w      = (const float*)d_in[8];
    const float* out_proj_w   = (const float*)d_in[9];
    const float* final_norm_w = (const float*)d_in[10];
    float* out = (float*)d_out;

    float *ph, *pzx, *pxbc, *pyp, *pac, *pse, *pss;
    uint4 *pwin, *pwout, *pemb, *phpk, *pypk;
    cudaGetSymbolAddress((void**)&ph,    g_h);
    cudaGetSymbolAddress((void**)&pzx,   g_zx);
    cudaGetSymbolAddress((void**)&pxbc,  g_xbc);
    cudaGetSymbolAddress((void**)&pyp,   g_yp);
    cudaGetSymbolAddress((void**)&pac,   g_acum);
    cudaGetSymbolAddress((void**)&pse,   g_send);
    cudaGetSymbolAddress((void**)&pss,   g_sstart);
    cudaGetSymbolAddress((void**)&pwin,  g_win_pk);
    cudaGetSymbolAddress((void**)&pwout, g_wout_pk);
    cudaGetSymbolAddress((void**)&pemb,  g_emb_pk);
    cudaGetSymbolAddress((void**)&phpk,  g_h_pk);
    cudaGetSymbolAddress((void**)&pypk,  g_y_pk);
    uint32_t* phpk32 = (uint32_t*)phpk;
    uint32_t* pypk32 = (uint32_t*)pypk;

    auto gemm_big   = gemm_t<128, 128, 2, 4>;
    auto gemm_nar   = gemm_t<128, 64,  4, 2>;
    auto gemm_small = gemm_t<64,  64,  2, 4>;
    const int SM_BIG = 3 * (128 + 128) * 8 * 16;
    const int SM_NAR = 3 * (128 + 64) * 8 * 16;
    const int SM_SML = 3 * (64 + 64) * 8 * 16;
    const int SM_COR = (DSTATE * 64 + 64 * DSTATE) * 4;
    cudaFuncSetAttribute(gemm_big, cudaFuncAttributeMaxDynamicSharedMemorySize,
                         SM_BIG);
    cudaFuncSetAttribute(gemm_nar, cudaFuncAttributeMaxDynamicSharedMemorySize,
                         SM_NAR);
    cudaFuncSetAttribute(gemm_small, cudaFuncAttributeMaxDynamicSharedMemorySize,
                         SM_SML);
    cudaFuncSetAttribute(correct_kernel,
                         cudaFuncAttributeMaxDynamicSharedMemorySize, SM_COR);

    const int WIN_W  = (NPAD_IN / 8) * (DIM / 32) * 32;
    const int WOUT_W = (DIM / 8) * (DINNER / 32) * 32;
    const int EMB_W  = (VOCAB / 8) * (DIM / 32) * 32;

    // launch order: 4th launch = conv_ch_kernel (ncu capture slot)
    embed_kernel<<<BT, 256>>>(x, embed, ph, phpk32);
    pack_b<<<WIN_W / 256, 256>>>(in_proj_w, pwin, DIM, DINPROJ);

    for (int l = 0; l < DEPTH; l++) {
        gemm_big<<<dim3(NPAD_IN / 128, BT / 128), 256, SM_BIG>>>(
            DINPROJ, DIM, phpk, pwin + (size_t)l * WIN_W, nullptr, pzx,
            nullptr);
        conv_ch_kernel<<<dim3(CONVCH / 256, TT / 64, BB), 256>>>(
            pzx, conv_w + (size_t)l * CONVCH * 4, conv_b + (size_t)l * CONVCH,
            pxbc);
        scan_seg_kernel<<<dim3(NSEG, NHEADS, BB), 512>>>(
            pxbc, pzx, dt_bias + l * NHEADS, A_log + l * NHEADS,
            Dw + l * NHEADS, pyp, pac, pse);
        propagate_kernel<<<dim3(NHEADS, BB), 256>>>(pse, pac, pss);
        correct_kernel<<<dim3(NSEG - 1, NHEADS, BB), 256, SM_COR>>>(
            pss, pac, pxbc, pyp);
        pack_b<<<WOUT_W / 256, 256>>>(out_proj_w + (size_t)l * DIM * DINNER,
                                      pwout + (size_t)l * WOUT_W, DINNER, DIM);
        if (l + 1 < DEPTH)
            pack_b<<<WIN_W / 256, 256>>>(
                in_proj_w + (size_t)(l + 1) * DINPROJ * DIM,
                pwin + (size_t)(l + 1) * WIN_W, DIM, DINPROJ);
        rmsgate_kernel<<<BT, 256>>>(pyp, pzx, gnorm_w + (size_t)l * DINNER,
                                    pypk32);
        gemm_nar<<<dim3(DIM / 64, BT / 128), 256, SM_NAR>>>(
            DIM, DINNER, pypk, pwout + (size_t)l * WOUT_W, ph, ph, phpk32);
    }

    rmsnorm_kernel<<<BT, 256>>>(ph, final_norm_w, DIM, phpk32);
    pack_b<<<EMB_W / 256, 256>>>(embed, pemb, DIM, VOCAB);
    gemm_small<<<dim3(VOCAB / 64, BT / 64), 256, SM_SML>>>(
        VOCAB, DIM, phpk, pemb, nullptr, out, nullptr);
}

// round 16
// speedup vs baseline: 1.9745x; 1.9745x over previous
#include <cuda_runtime.h>
#include <cuda_fp16.h>
#include <math.h>
#include <stdint.h>

#define BB 2
#define TT 1024
#define DIM 1024
#define DEPTH 2
#define DSTATE 128
#define HEADDIM 64
#define NHEADS 32
#define DINNER 2048
#define CONVCH 2304
#define DINPROJ 4384
#define NPAD_IN 4480          // 35*128 padded in_proj rows
#define VOCAB 256
#define BT (BB*TT)
#define NSEG 8
#define TSEG (TT/NSEG)        // 128

// ---------------- scratch (device globals; no allocations allowed) ----------
__device__ float g_h  [BT * DIM];
__device__ float g_zx [BT * DINPROJ];
__device__ float g_xbc[BT * CONVCH];       // conv+silu output
__device__ float g_yp [4 * BT * DINNER];   // scan partials, 4 n-quarters
__device__ float g_acum [BB * NHEADS * TT];
__device__ float g_send [BB * NHEADS * NSEG * 64 * DSTATE];
__device__ float g_sstart[BB * NHEADS * (NSEG-1) * 64 * DSTATE];
// fragment-packed fp16 operands
__device__ uint4 g_win_pk [DEPTH * (NPAD_IN/8) * (DIM/32)    * 32];
__device__ uint4 g_wout_pk[DEPTH * (DIM/8)     * (DINNER/32) * 32];
__device__ uint4 g_emb_pk [(VOCAB/8) * (DIM/32) * 32];
__device__ uint4 g_h_pk   [(BT/16) * (DIM/16)    * 32];
__device__ uint4 g_y_pk   [(BT/16) * (DINNER/16) * 32];

// ---------------- helpers ----------------
__device__ __forceinline__ uint32_t h2u(float lo, float hi) {
    __half2 h = __floats2half2_rn(lo, hi);
    return *(uint32_t*)&h;
}
__device__ __forceinline__ void pk_store(uint32_t* __restrict__ P, int K,
                                         int m, int c, float lo, float hi) {
    int word = (((m >> 4) * (K >> 4) + (c >> 4)) << 5) + ((m & 7) << 2) +
               ((c >> 1) & 3);
    P[(word << 2) + ((m >> 3) & 1) + (((c >> 3) & 1) << 1)] = h2u(lo, hi);
}
__device__ __forceinline__ void mma_f16(float* c,
                                        uint32_t a0, uint32_t a1,
                                        uint32_t a2, uint32_t a3,
                                        uint32_t b0, uint32_t b1) {
    asm volatile(
        "mma.sync.aligned.m16n8k16.row.col.f32.f16.f16.f32 "
        "{%0,%1,%2,%3}, {%4,%5,%6,%7}, {%8,%9}, {%0,%1,%2,%3};"
        : "+f"(c[0]), "+f"(c[1]), "+f"(c[2]), "+f"(c[3])
        : "r"(a0), "r"(a1), "r"(a2), "r"(a3), "r"(b0), "r"(b1));
}
__device__ __forceinline__ void cpa16(uint32_t dst, const void* src) {
    asm volatile("cp.async.cg.shared.global [%0], [%1], 16;"
                 :: "r"(dst), "l"(src));
}
__device__ __forceinline__ void cpa4(uint32_t dst, const void* src) {
    asm volatile("cp.async.ca.shared.global [%0], [%1], 4;"
                 :: "r"(dst), "l"(src));
}
__device__ __forceinline__ uint32_t smem_u32(const void* p) {
    uint32_t a;
    asm("{ .reg .u64 t; cvta.to.shared.u64 t, %1; cvt.u32.u64 %0, t; }"
        : "=r"(a) : "l"(p));
    return a;
}

// ---------------- weight pack: fp32 [Nsrc,K] -> fp16 fragment order --------
__global__ void pack_b(const float* __restrict__ B, uint4* __restrict__ P,
                       int K, int Nsrc) {
    int idx  = blockIdx.x * 256 + threadIdx.x;
    int lane = idx & 31;
    int t2   = idx >> 5;
    int kpn  = K >> 5;
    int kp   = t2 % kpn;
    int nt   = t2 / kpn;
    int g = lane >> 2, q = lane & 3;
    int n  = nt * 8 + g;
    uint4 w = make_uint4(0u, 0u, 0u, 0u);
    if (n < Nsrc) {
        const float* r = B + (size_t)n * K + kp * 32 + 2 * q;
        float2 f0 = *(const float2*)r;
        float2 f1 = *(const float2*)(r + 8);
        float2 f2 = *(const float2*)(r + 16);
        float2 f3 = *(const float2*)(r + 24);
        w = make_uint4(h2u(f0.x, f0.y), h2u(f1.x, f1.y),
                       h2u(f2.x, f2.y), h2u(f3.x, f3.y));
    }
    P[idx] = w;
}

// ---------------- embedding gather (fp32 + packed fp16) ----------------
__global__ void embed_kernel(const int* __restrict__ x,
                             const float* __restrict__ embed,
                             float* __restrict__ h,
                             uint32_t* __restrict__ hpk) {
    int bt  = blockIdx.x;
    int tok = x[bt];
    const float4* src = (const float4*)(embed + (size_t)tok * DIM);
    float4 v = src[threadIdx.x];
    ((float4*)(h + (size_t)bt * DIM))[threadIdx.x] = v;
    int c0 = threadIdx.x * 4;
    pk_store(hpk, DIM, bt, c0,     v.x, v.y);
    pk_store(hpk, DIM, bt, c0 + 2, v.z, v.w);
}

// ---------------- templated packed fp16 GEMM (R12-proven) ------------------
template<int BM, int BN, int WM, int WN>
__global__ void __launch_bounds__(256, 2)
gemm_t(int N, int K,
       const uint4* __restrict__ Apk,
       const uint4* __restrict__ Bpk,
       const float* __restrict__ Res,
       float* __restrict__ C,
       uint32_t* __restrict__ Cpk) {
    constexpr int MT  = BM / 16 / WM;
    constexpr int NT  = BN / 8 / WN;
    constexpr int AW  = BM * 8;
    constexpr int BW  = BN * 8;
    constexpr int STW = AW + BW;
    constexpr int NA  = AW / 256;
    constexpr int NB  = BW / 256;
    extern __shared__ uint4 sm4[];
    const uint32_t sbase = smem_u32(sm4);

    const int tid    = threadIdx.x;
    const int lane   = tid & 31;
    const int wid    = tid >> 5;
    const int warp_m = wid / WN;
    const int warp_n = wid % WN;
    const int g      = lane >> 2;
    const int q      = lane & 3;
    const int row0   = blockIdx.y * BM;
    const int col0   = blockIdx.x * BN;
    const int ktn16  = K >> 4;
    const int kpn    = K >> 5;
    const int ktn    = K >> 6;

    const uint4* asrc[NA]; uint32_t adst[NA];
    const uint4* bsrc[NB]; uint32_t bdst[NB];
#pragma unroll
    for (int i = 0; i < NA; i++) {
        int ca = tid + 256 * i, la = ca & 31, r = ca >> 5;
        int ksl = r & 3, mti = r >> 2;
        asrc[i] = Apk + ((size_t)(row0 / 16 + mti) * ktn16 + ksl) * 32 + la;
        adst[i] = ca;
    }
#pragma unroll
    for (int i = 0; i < NB; i++) {
        int cb = tid + 256 * i, la = cb & 31, r = cb >> 5;
        int kpl = r & 1, nti = r >> 1;
        bsrc[i] = Bpk + ((size_t)(col0 / 8 + nti) * kpn + kpl) * 32 + la;
        bdst[i] = AW + cb;
    }

    float acc[MT][NT][4];
#pragma unroll
    for (int i = 0; i < MT; i++)
#pragma unroll
        for (int j = 0; j < NT; j++)
#pragma unroll
            for (int r = 0; r < 4; r++) acc[i][j][r] = 0.f;

#pragma unroll
    for (int p = 0; p < 2; p++) {
        uint32_t sb = sbase + p * STW * 16;
#pragma unroll
        for (int i = 0; i < NA; i++) cpa16(sb + adst[i] * 16, asrc[i] + p * 128);
#pragma unroll
        for (int i = 0; i < NB; i++) cpa16(sb + bdst[i] * 16, bsrc[i] + p * 64);
        asm volatile("cp.async.commit_group;");
    }

    for (int kt = 0; kt < ktn; kt++) {
        asm volatile("cp.async.wait_group 1;");
        __syncthreads();

        if (kt + 2 < ktn) {
            uint32_t sb = sbase + ((kt + 2) % 3) * STW * 16;
            size_t ao = (size_t)(kt + 2) * 128;
            size_t bo = (size_t)(kt + 2) * 64;
#pragma unroll
            for (int i = 0; i < NA; i++) cpa16(sb + adst[i] * 16, asrc[i] + ao);
#pragma unroll
            for (int i = 0; i < NB; i++) cpa16(sb + bdst[i] * 16, bsrc[i] + bo);
        }
        asm volatile("cp.async.commit_group;");

        const uint4* Ab = sm4 + (kt % 3) * STW;
        const uint4* Bb = Ab + AW;
#pragma unroll
        for (int kp = 0; kp < 2; kp++) {
            uint4 bw[NT];
#pragma unroll
            for (int nt = 0; nt < NT; nt++)
                bw[nt] = Bb[((warp_n * NT + nt) * 2 + kp) * 32 + lane];
#pragma unroll
            for (int hl = 0; hl < 2; hl++) {
                const int ks = kp * 2 + hl;
                uint4 af[MT];
#pragma unroll
                for (int mt = 0; mt < MT; mt++)
                    af[mt] = Ab[((warp_m * MT + mt) * 4 + ks) * 32 + lane];
#pragma unroll
                for (int mt = 0; mt < MT; mt++)
#pragma unroll
                    for (int nt = 0; nt < NT; nt++) {
                        uint32_t b0 = hl ? bw[nt].z : bw[nt].x;
                        uint32_t b1 = hl ? bw[nt].w : bw[nt].y;
                        mma_f16(acc[mt][nt], af[mt].x, af[mt].y, af[mt].z,
                                af[mt].w, b0, b1);
                    }
            }
        }
    }

#pragma unroll
    for (int mt = 0; mt < MT; mt++) {
        int r_lo = row0 + (warp_m * MT + mt) * 16 + g;
#pragma unroll
        for (int nt = 0; nt < NT; nt++) {
            int c = col0 + (warp_n * NT + nt) * 8 + q * 2;
            if (c < N) {
                float2 v0 = make_float2(acc[mt][nt][0], acc[mt][nt][1]);
                float2 v1 = make_float2(acc[mt][nt][2], acc[mt][nt][3]);
                size_t o0 = (size_t)r_lo * N + c;
                size_t o1 = (size_t)(r_lo + 8) * N + c;
                if (Res) {
                    float2 r0v = *(const float2*)(Res + o0);
                    float2 r1v = *(const float2*)(Res + o1);
                    v0.x += r0v.x; v0.y += r0v.y;
                    v1.x += r1v.x; v1.y += r1v.y;
                }
                *(float2*)(C + o0) = v0;
                *(float2*)(C + o1) = v1;
                if (Cpk) {
                    pk_store(Cpk, N, r_lo,     c, v0.x, v0.y);
                    pk_store(Cpk, N, r_lo + 8, c, v1.x, v1.y);
                }
            }
        }
    }
}

// ---------------- causal conv (K=4) + SiLU, channel-per-thread -------------
// 32-step t-tiles for 2x parallelism (latency-bound at 64).
__global__ void __launch_bounds__(256)
conv_ch_kernel(const float* __restrict__ zx,
               const float* __restrict__ cw,
               const float* __restrict__ cb,
               float* __restrict__ xbc) {
    const int ch = blockIdx.x * 256 + threadIdx.x;
    const int t0 = blockIdx.y * 32;
    const int b  = blockIdx.z;
    float4 w = *(const float4*)(cw + ch * 4);
    float bias = cb[ch];
    const float* src = zx + (size_t)(b * TT) * DINPROJ + DINNER + ch;
    float* dst = xbc + (size_t)(b * TT) * CONVCH + ch;
    float x0 = 0.f, x1 = 0.f, x2 = 0.f;
    if (t0 >= 3) {
        x0 = src[(size_t)(t0 - 3) * DINPROJ];
        x1 = src[(size_t)(t0 - 2) * DINPROJ];
        x2 = src[(size_t)(t0 - 1) * DINPROJ];
    }
#pragma unroll 4
    for (int t = t0; t < t0 + 32; t++) {
        float x3 = src[(size_t)t * DINPROJ];
        float acc = fmaf(x0, w.x, fmaf(x1, w.y, fmaf(x2, w.z,
                         fmaf(x3, w.w, bias))));
        acc = acc / (1.f + expf(-acc));
        dst[(size_t)t * CONVCH] = acc;
        x0 = x1; x1 = x2; x2 = x3;
    }
}

// ---------------- segmented SSM scan pass 1 (conv'd input) -----------------
// CTA per (seg, nh, h, b) => 4*NSEG x NHEADS x BB CTAs. Double-buffered.
#define SCH 16
__global__ void __launch_bounds__(256)
scan_seg_kernel(const float* __restrict__ xbc,
                const float* __restrict__ zx,
                const float* __restrict__ dtb,
                const float* __restrict__ alog,
                const float* __restrict__ Dw,
                float* __restrict__ yp,
                float* __restrict__ acum,
                float* __restrict__ send) {
    __shared__ float Xs [2][SCH][64];
    __shared__ float Bss[2][SCH][32];
    __shared__ float Css[2][SCH][32];
    __shared__ float DTraw[2][SCH];
    __shared__ float As[SCH], Dts[SCH];

    const int tid  = threadIdx.x;
    const int nh   = blockIdx.x & 3;
    const int seg  = blockIdx.x >> 2;
    const int h    = blockIdx.y;
    const int b    = blockIdx.z;
    const int lane = tid & 31;
    const int wid  = tid >> 5;
    const int pl   = lane >> 2;
    const int nq   = lane & 3;
    const int p    = wid * 8 + pl;

    const int xoff = h * 64;
    const int boff = DINNER + nh * 32;
    const int coff = DINNER + DSTATE + nh * 32;

    const uint32_t xs_s = smem_u32(&Xs[0][0][0]);
    const uint32_t bs_s = smem_u32(&Bss[0][0][0]);
    const uint32_t cs_s = smem_u32(&Css[0][0][0]);
    const uint32_t dt_s = smem_u32(&DTraw[0][0]);

    float s[8];
#pragma unroll
    for (int i = 0; i < 8; i++) s[i] = 0.f;
    const float dtbv = dtb[h];
    const float aexp = expf(alog[h]);
    const float Dh   = (nh == 0) ? Dw[h] : 0.f;
    const float* xrow = xbc + (size_t)b * TT * CONVCH;
    const float* zrow = zx + (size_t)b * TT * DINPROJ;
    float* yout = yp + ((size_t)nh * BT + (size_t)b * TT) * DINNER + h * 64;
    float* acrow = acum + (size_t)(b * NHEADS + h) * TT;
    float carry = 1.f;

    // stage one chunk into buffer `buf`: 512 float4 (X 256, B 128, C 128)
    auto stage = [&](int t0, int buf) {
#pragma unroll
        for (int k = 0; k < 2; k++) {
            int j = tid + 256 * k;
            int tt, q4, choff;
            uint32_t dst;
            if (j < 256) {
                tt = j >> 4; q4 = j & 15;
                choff = xoff + q4 * 4;
                dst = xs_s + (buf * SCH * 64 + tt * 64 + q4 * 4) * 4;
            } else if (j < 384) {
                int jj = j - 256; tt = jj >> 3; q4 = jj & 7;
                choff = boff + q4 * 4;
                int p4 = (((q4 & 1) << 2) + (q4 >> 1)) * 4;
                dst = bs_s + (buf * SCH * 32 + tt * 32 + p4) * 4;
            } else {
                int jj = j - 384; tt = jj >> 3; q4 = jj & 7;
                choff = coff + q4 * 4;
                int p4 = (((q4 & 1) << 2) + (q4 >> 1)) * 4;
                dst = cs_s + (buf * SCH * 32 + tt * 32 + p4) * 4;
            }
            cpa16(dst, xrow + (size_t)(t0 + tt) * CONVCH + choff);
        }
        if (tid < SCH)
            cpa4(dt_s + (buf * SCH + tid) * 4,
                 zrow + (size_t)(t0 + tid) * DINPROJ + (DINNER + CONVCH) + h);
    };

    const int tstart = seg * TSEG;
    stage(tstart, 0);
    asm volatile("cp.async.commit_group;");

    const int nchunks = TSEG / SCH;
    for (int c = 0; c < nchunks; c++) {
        const int buf = c & 1;
        const int t0 = tstart + c * SCH;
        if (c + 1 < nchunks) stage(t0 + SCH, buf ^ 1);
        asm volatile("cp.async.commit_group;");
        asm volatile("cp.async.wait_group 1;");
        __syncthreads();

        if (tid < SCH) {
            float v = DTraw[buf][tid] + dtbv;
            float d = (v > 20.f) ? v : log1pf(expf(v));
            Dts[tid] = d;
            As[tid]  = expf(-aexp * d);
        }
        __syncthreads();

        if (nh == 0 && tid == 0) {
            float cc = carry;
#pragma unroll
            for (int tt = 0; tt < SCH; tt++) {
                cc *= As[tt];
                acrow[t0 + tt] = cc;
            }
            carry = cc;
        }

#pragma unroll
        for (int tt = 0; tt < SCH; tt++) {
            const float da   = As[tt];
            const float xv   = Xs[buf][tt][p];
            const float coef = Dts[tt] * xv;
            const float4* B4 = (const float4*)&Bss[buf][tt][0];
            const float4* C4 = (const float4*)&Css[buf][tt][0];
            float part = 0.f;
#pragma unroll
            for (int i4 = 0; i4 < 2; i4++) {
                float4 bv = B4[i4 * 4 + nq];
                float4 cv = C4[i4 * 4 + nq];
                float* sp = s + i4 * 4;
                sp[0] = fmaf(da, sp[0], coef * bv.x);
                sp[1] = fmaf(da, sp[1], coef * bv.y);
                sp[2] = fmaf(da, sp[2], coef * bv.z);
                sp[3] = fmaf(da, sp[3], coef * bv.w);
                part = fmaf(sp[0], cv.x, part);
                part = fmaf(sp[1], cv.y, part);
                part = fmaf(sp[2], cv.z, part);
                part = fmaf(sp[3], cv.w, part);
            }
            part += __shfl_xor_sync(0xFFFFFFFFu, part, 1);
            part += __shfl_xor_sync(0xFFFFFFFFu, part, 2);
            if (nq == 0)
                yout[(size_t)(t0 + tt) * DINNER + p] = fmaf(Dh, xv, part);
        }
        __syncthreads();
    }

    // ---- write local end state in natural n order ----
#pragma unroll
    for (int i4 = 0; i4 < 2; i4++) {
        int gidx = i4 * 4 + nq;
        int q4   = ((gidx & 3) << 1) | (gidx >> 2);
#pragma unroll
        for (int j = 0; j < 4; j++) {
            int ng = nh * 32 + q4 * 4 + j;
            send[((size_t)((b * NHEADS + h) * NSEG + seg) * 64 + p) * DSTATE +
                 ng] = s[i4 * 4 + j];
        }
    }
}

// ---------------- pass 2: propagate segment init states (generic NSEG) -----
__global__ void propagate_kernel(const float* __restrict__ send,
                                 const float* __restrict__ acum,
                                 float* __restrict__ sstart) {
    const int h = blockIdx.x, b = blockIdx.y;
    const size_t base = (size_t)(b * NHEADS + h);
    const float* se = send + base * NSEG * 64 * DSTATE;
    float* ss = sstart + base * (NSEG - 1) * 64 * DSTATE;
    const float* ac = acum + base * TT;
    const int SEGSZ = 64 * DSTATE;
    for (int e = threadIdx.x; e < SEGSZ; e += 256) {
        float s = se[e];                 // S_start for segment 1
        ss[e] = s;
#pragma unroll
        for (int sg = 2; sg < NSEG; sg++) {
            float aT = ac[sg * TSEG - 1];       // A_total of segment sg-1
            s = aT * s + se[(size_t)(sg - 1) * SEGSZ + e];
            ss[(size_t)(sg - 1) * SEGSZ + e] = s;
        }
    }
}

// ---------------- pass 3: correction y += A_cum * (C . S_start) ------------
__global__ void __launch_bounds__(256)
correct_kernel(const float* __restrict__ sstart,
               const float* __restrict__ acum,
               const float* __restrict__ xbc,
               float* __restrict__ yp) {
    extern __shared__ float psm[];
    float* Ssm = psm;                // [n][p] : DSTATE x 64
    float* Csm = psm + DSTATE * 64;  // [tt][n] : 64 x DSTATE
    const int sg  = blockIdx.x;
    const int seg = sg + 1;
    const int h   = blockIdx.y;
    const int b   = blockIdx.z;

    const float* S = sstart +
        ((size_t)(b * NHEADS + h) * (NSEG - 1) + sg) * 64 * DSTATE;
    for (int e = threadIdx.x; e < 64 * DSTATE; e += 256) {
        int p = e >> 7, n = e & 127;
        Ssm[n * 64 + p] = S[e];
    }

    const int p  = threadIdx.x & 63;
    const int tg = threadIdx.x >> 6;
    const float* ac = acum + (size_t)(b * NHEADS + h) * TT + seg * TSEG;

    for (int blk = 0; blk < TSEG / 64; blk++) {
        __syncthreads();
        for (int e = threadIdx.x; e < 64 * DSTATE / 4; e += 256) {
            int tt = e >> 5, n4 = e & 31;
            ((float4*)(Csm + tt * DSTATE))[n4] =
                ((const float4*)(xbc +
                    (size_t)(b * TT + seg * TSEG + blk * 64 + tt) * CONVCH +
                    DINNER + DSTATE))[n4];
        }
        __syncthreads();
#pragma unroll 4
        for (int i = 0; i < 16; i++) {
            int tl = i * 4 + tg;
            int t  = seg * TSEG + blk * 64 + tl;
            float a = ac[blk * 64 + tl];
            const float4* Cr = (const float4*)(Csm + tl * DSTATE);
            float dot = 0.f;
#pragma unroll
            for (int n4 = 0; n4 < 32; n4++) {
                float4 cv = Cr[n4];
                dot = fmaf(cv.x, Ssm[(n4 * 4 + 0) * 64 + p], dot);
                dot = fmaf(cv.y, Ssm[(n4 * 4 + 1) * 64 + p], dot);
                dot = fmaf(cv.z, Ssm[(n4 * 4 + 2) * 64 + p], dot);
                dot = fmaf(cv.w, Ssm[(n4 * 4 + 3) * 64 + p], dot);
            }
            float* yptr = yp + (size_t)(b * TT + t) * DINNER + h * 64 + p;
            *yptr += a * dot;
        }
    }
}

// ---------------- fused gate + RMSNorm + packed write ----------------------
__global__ void __launch_bounds__(256)
rmsgate_kernel(const float* __restrict__ yp,
               const float* __restrict__ zx,
               const float* __restrict__ w,
               uint32_t* __restrict__ ypk) {
    __shared__ float vc[DINNER];
    __shared__ float sh[9];
    const int bt = blockIdx.x;
    const size_t L = (size_t)BT * DINNER;
    const float* r0 = yp + (size_t)bt * DINNER;
    const float* zr = zx + (size_t)bt * DINPROJ;

    float ss = 0.f;
    for (int i = threadIdx.x * 2; i < DINNER; i += 512) {
        float2 a0 = *(const float2*)(r0 + i);
        float2 a1 = *(const float2*)(r0 + L + i);
        float2 a2 = *(const float2*)(r0 + 2 * L + i);
        float2 a3 = *(const float2*)(r0 + 3 * L + i);
        float2 z2 = *(const float2*)(zr + i);
        float y0 = a0.x + a1.x + a2.x + a3.x;
        float y1 = a0.y + a1.y + a2.y + a3.y;
        float v0 = y0 * (z2.x / (1.f + expf(-z2.x)));
        float v1 = y1 * (z2.y / (1.f + expf(-z2.y)));
        vc[i] = v0; vc[i + 1] = v1;
        ss = fmaf(v0, v0, fmaf(v1, v1, ss));
    }
#pragma unroll
    for (int o = 16; o; o >>= 1) ss += __shfl_xor_sync(0xFFFFFFFFu, ss, o);
    int wd = threadIdx.x >> 5, lane = threadIdx.x & 31;
    if (lane == 0) sh[wd] = ss;
    __syncthreads();
    if (wd == 0) {
        float v = (lane < 8) ? sh[lane] : 0.f;
#pragma unroll
        for (int o = 16; o; o >>= 1) v += __shfl_xor_sync(0xFFFFFFFFu, v, o);
        if (lane == 0) sh[8] = rsqrtf(v / DINNER + 1e-5f);
    }
    __syncthreads();
    float sc = sh[8];
    for (int i = threadIdx.x * 2; i < DINNER; i += 512) {
        float o0 = vc[i] * sc * w[i];
        float o1 = vc[i + 1] * sc * w[i + 1];
        pk_store(ypk, DINNER, bt, i, o0, o1);
    }
}

// ---------------- final RMSNorm (+ packed write) ----------------
__global__ void rmsnorm_kernel(float* __restrict__ data,
                               const float* __restrict__ w, int n,
                               uint32_t* __restrict__ pk) {
    float* r = data + (size_t)blockIdx.x * n;
    float ss = 0.f;
    for (int i = threadIdx.x; i < n; i += blockDim.x) {
        float v = r[i];
        ss = fmaf(v, v, ss);
    }
#pragma unroll
    for (int o = 16; o; o >>= 1) ss += __shfl_xor_sync(0xFFFFFFFFu, ss, o);
    __shared__ float sh[9];
    int wd = threadIdx.x >> 5, lane = threadIdx.x & 31;
    if (lane == 0) sh[wd] = ss;
    __syncthreads();
    if (wd == 0) {
        float v = (lane < 8) ? sh[lane] : 0.f;
#pragma unroll
        for (int o = 16; o; o >>= 1) v += __shfl_xor_sync(0xFFFFFFFFu, v, o);
        if (lane == 0) sh[8] = rsqrtf(v / n + 1e-5f);
    }
    __syncthreads();
    float sc = sh[8];
    for (int i = threadIdx.x * 2; i < n; i += 2 * blockDim.x) {
        float o0 = r[i] * sc * w[i];
        float o1 = r[i + 1] * sc * w[i + 1];
        r[i] = o0; r[i + 1] = o1;
        pk_store(pk, n, blockIdx.x, i, o0, o1);
    }
}

// ---------------- launcher ----------------
extern "C" void kernel_launch(void* const* d_in, const int* in_sizes, int n_in,
                              void* d_out, int out_size) {
    const int*   x            = (const int*)  d_in[0];
    const float* embed        = (const float*)d_in[1];
    const float* in_proj_w    = (const float*)d_in[2];
    const float* conv_w       = (const float*)d_in[3];
    const float* conv_b       = (const float*)d_in[4];
    const float* dt_bias      = (const float*)d_in[5];
    const float* A_log        = (const float*)d_in[6];
    const float* Dw           = (const float*)d_in[7];
    const float* gnorm_w      = (const float*)d_in[8];
    const float* out_proj_w   = (const float*)d_in[9];
    const float* final_norm_w = (const float*)d_in[10];
    float* out = (float*)d_out;

    float *ph, *pzx, *pxbc, *pyp, *pac, *pse, *pss;
    uint4 *pwin, *pwout, *pemb, *phpk, *pypk;
    cudaGetSymbolAddress((void**)&ph,    g_h);
    cudaGetSymbolAddress((void**)&pzx,   g_zx);
    cudaGetSymbolAddress((void**)&pxbc,  g_xbc);
    cudaGetSymbolAddress((void**)&pyp,   g_yp);
    cudaGetSymbolAddress((void**)&pac,   g_acum);
    cudaGetSymbolAddress((void**)&pse,   g_send);
    cudaGetSymbolAddress((void**)&pss,   g_sstart);
    cudaGetSymbolAddress((void**)&pwin,  g_win_pk);
    cudaGetSymbolAddress((void**)&pwout, g_wout_pk);
    cudaGetSymbolAddress((void**)&pemb,  g_emb_pk);
    cudaGetSymbolAddress((void**)&phpk,  g_h_pk);
    cudaGetSymbolAddress((void**)&pypk,  g_y_pk);
    uint32_t* phpk32 = (uint32_t*)phpk;
    uint32_t* pypk32 = (uint32_t*)pypk;

    auto gemm_big   = gemm_t<128, 128, 2, 4>;
    auto gemm_nar   = gemm_t<128, 64,  4, 2>;
    auto gemm_small = gemm_t<64,  64,  2, 4>;
    const int SM_BIG = 3 * (128 + 128) * 8 * 16;
    const int SM_NAR = 3 * (128 + 64) * 8 * 16;
    const int SM_SML = 3 * (64 + 64) * 8 * 16;
    const int SM_COR = (DSTATE * 64 + 64 * DSTATE) * 4;
    cudaFuncSetAttribute(gemm_big, cudaFuncAttributeMaxDynamicSharedMemorySize,
                         SM_BIG);
    cudaFuncSetAttribute(gemm_nar, cudaFuncAttributeMaxDynamicSharedMemorySize,
                         SM_NAR);
    cudaFuncSetAttribute(gemm_small, cudaFuncAttributeMaxDynamicSharedMemorySize,
                         SM_SML);
    cudaFuncSetAttribute(correct_kernel,
                         cudaFuncAttributeMaxDynamicSharedMemorySize, SM_COR);

    const int WIN_W  = (NPAD_IN / 8) * (DIM / 32) * 32;
    const int WOUT_W = (DIM / 8) * (DINNER / 32) * 32;
    const int EMB_W  = (VOCAB / 8) * (DIM / 32) * 32;

    embed_kernel<<<BT, 256>>>(x, embed, ph, phpk32);
    pack_b<<<WIN_W / 256, 256>>>(in_proj_w, pwin, DIM, DINPROJ);

    for (int l = 0; l < DEPTH; l++) {
        gemm_big<<<dim3(NPAD_IN / 128, BT / 128), 256, SM_BIG>>>(
            DINPROJ, DIM, phpk, pwin + (size_t)l * WIN_W, nullptr, pzx,
            nullptr);
        conv_ch_kernel<<<dim3(CONVCH / 256, TT / 32, BB), 256>>>(
            pzx, conv_w + (size_t)l * CONVCH * 4, conv_b + (size_t)l * CONVCH,
            pxbc);
        scan_seg_kernel<<<dim3(4 * NSEG, NHEADS, BB), 256>>>(
            pxbc, pzx, dt_bias + l * NHEADS, A_log + l * NHEADS,
            Dw + l * NHEADS, pyp, pac, pse);
        propagate_kernel<<<dim3(NHEADS, BB), 256>>>(pse, pac, pss);
        correct_kernel<<<dim3(NSEG - 1, NHEADS, BB), 256, SM_COR>>>(
            pss, pac, pxbc, pyp);
        pack_b<<<WOUT_W / 256, 256>>>(out_proj_w + (size_t)l * DIM * DINNER,
                                      pwout + (size_t)l * WOUT_W, DINNER, DIM);
        if (l + 1 < DEPTH)
            pack_b<<<WIN_W / 256, 256>>>(
                in_proj_w + (size_t)(l + 1) * DINPROJ * DIM,
                pwin + (size_t)(l + 1) * WIN_W, DIM, DINPROJ);
        rmsgate_kernel<<<BT, 256>>>(pyp, pzx, gnorm_w + (size_t)l * DINNER,
                                    pypk32);
        gemm_nar<<<dim3(DIM / 64, BT / 128), 256, SM_NAR>>>(
            DIM, DINNER, pypk, pwout + (size_t)l * WOUT_W, ph, ph, phpk32);
    }

    rmsnorm_kernel<<<BT, 256>>>(ph, final_norm_w, DIM, phpk32);
    pack_b<<<EMB_W / 256, 256>>>(embed, pemb, DIM, VOCAB);
    gemm_small<<<dim3(VOCAB / 64, BT / 64), 256, SM_SML>>>(
        VOCAB, DIM, phpk, pemb, nullptr, out, nullptr);
}

// round 17
// speedup vs baseline: 1.9973x; 1.0115x over previous
#include <cuda_runtime.h>
#include <cuda_fp16.h>
#include <math.h>
#include <stdint.h>

#define BB 2
#define TT 1024
#define DIM 1024
#define DEPTH 2
#define DSTATE 128
#define HEADDIM 64
#define NHEADS 32
#define DINNER 2048
#define CONVCH 2304
#define DINPROJ 4384
#define NPAD_IN 4480          // 35*128 padded in_proj rows
#define VOCAB 256
#define BT (BB*TT)
#define NSEG 8
#define TSEG (TT/NSEG)        // 128

typedef unsigned long long ull;

// ---------------- scratch (device globals; no allocations allowed) ----------
__device__ float g_h  [BT * DIM];
__device__ float g_zx [BT * DINPROJ];
__device__ float g_xbc[BT * CONVCH];       // conv+silu output
__device__ float g_yp [4 * BT * DINNER];   // scan partials, 4 n-quarters
__device__ float g_acum [BB * NHEADS * TT];
__device__ float g_send [BB * NHEADS * NSEG * 64 * DSTATE];
__device__ float g_sstart[BB * NHEADS * (NSEG-1) * 64 * DSTATE];
// fragment-packed fp16 operands
__device__ uint4 g_win_pk [DEPTH * (NPAD_IN/8) * (DIM/32)    * 32];
__device__ uint4 g_wout_pk[DEPTH * (DIM/8)     * (DINNER/32) * 32];
__device__ uint4 g_emb_pk [(VOCAB/8) * (DIM/32) * 32];
__device__ uint4 g_h_pk   [(BT/16) * (DIM/16)    * 32];
__device__ uint4 g_y_pk   [(BT/16) * (DINNER/16) * 32];

// ---------------- helpers ----------------
__device__ __forceinline__ uint32_t h2u(float lo, float hi) {
    __half2 h = __floats2half2_rn(lo, hi);
    return *(uint32_t*)&h;
}
__device__ __forceinline__ void pk_store(uint32_t* __restrict__ P, int K,
                                         int m, int c, float lo, float hi) {
    int word = (((m >> 4) * (K >> 4) + (c >> 4)) << 5) + ((m & 7) << 2) +
               ((c >> 1) & 3);
    P[(word << 2) + ((m >> 3) & 1) + (((c >> 3) & 1) << 1)] = h2u(lo, hi);
}
__device__ __forceinline__ void mma_f16(float* c,
                                        uint32_t a0, uint32_t a1,
                                        uint32_t a2, uint32_t a3,
                                        uint32_t b0, uint32_t b1) {
    asm volatile(
        "mma.sync.aligned.m16n8k16.row.col.f32.f16.f16.f32 "
        "{%0,%1,%2,%3}, {%4,%5,%6,%7}, {%8,%9}, {%0,%1,%2,%3};"
        : "+f"(c[0]), "+f"(c[1]), "+f"(c[2]), "+f"(c[3])
        : "r"(a0), "r"(a1), "r"(a2), "r"(a3), "r"(b0), "r"(b1));
}
__device__ __forceinline__ void cpa16(uint32_t dst, const void* src) {
    asm volatile("cp.async.cg.shared.global [%0], [%1], 16;"
                 :: "r"(dst), "l"(src));
}
__device__ __forceinline__ void cpa4(uint32_t dst, const void* src) {
    asm volatile("cp.async.ca.shared.global [%0], [%1], 4;"
                 :: "r"(dst), "l"(src));
}
__device__ __forceinline__ uint32_t smem_u32(const void* p) {
    uint32_t a;
    asm("{ .reg .u64 t; cvta.to.shared.u64 t, %1; cvt.u32.u64 %0, t; }"
        : "=r"(a) : "l"(p));
    return a;
}
// ---- packed f32x2 (Blackwell) ----
__device__ __forceinline__ ull pk2(float lo, float hi) {
    ull r;
    asm("mov.b64 %0, {%1, %2};" : "=l"(r) : "f"(lo), "f"(hi));
    return r;
}
__device__ __forceinline__ void upk2(ull v, float& lo, float& hi) {
    asm("mov.b64 {%0, %1}, %2;" : "=f"(lo), "=f"(hi) : "l"(v));
}
__device__ __forceinline__ ull fma2(ull a, ull b, ull c) {
    ull d;
    asm("fma.rn.f32x2 %0, %1, %2, %3;" : "=l"(d) : "l"(a), "l"(b), "l"(c));
    return d;
}
__device__ __forceinline__ ull mul2(ull a, ull b) {
    ull d;
    asm("mul.rn.f32x2 %0, %1, %2;" : "=l"(d) : "l"(a), "l"(b));
    return d;
}

// ---------------- weight pack: fp32 [Nsrc,K] -> fp16 fragment order --------
__global__ void pack_b(const float* __restrict__ B, uint4* __restrict__ P,
                       int K, int Nsrc) {
    int idx  = blockIdx.x * 256 + threadIdx.x;
    int lane = idx & 31;
    int t2   = idx >> 5;
    int kpn  = K >> 5;
    int kp   = t2 % kpn;
    int nt   = t2 / kpn;
    int g = lane >> 2, q = lane & 3;
    int n  = nt * 8 + g;
    uint4 w = make_uint4(0u, 0u, 0u, 0u);
    if (n < Nsrc) {
        const float* r = B + (size_t)n * K + kp * 32 + 2 * q;
        float2 f0 = *(const float2*)r;
        float2 f1 = *(const float2*)(r + 8);
        float2 f2 = *(const float2*)(r + 16);
        float2 f3 = *(const float2*)(r + 24);
        w = make_uint4(h2u(f0.x, f0.y), h2u(f1.x, f1.y),
                       h2u(f2.x, f2.y), h2u(f3.x, f3.y));
    }
    P[idx] = w;
}

// ---------------- embedding gather (fp32 + packed fp16) ----------------
__global__ void embed_kernel(const int* __restrict__ x,
                             const float* __restrict__ embed,
                             float* __restrict__ h,
                             uint32_t* __restrict__ hpk) {
    int bt  = blockIdx.x;
    int tok = x[bt];
    const float4* src = (const float4*)(embed + (size_t)tok * DIM);
    float4 v = src[threadIdx.x];
    ((float4*)(h + (size_t)bt * DIM))[threadIdx.x] = v;
    int c0 = threadIdx.x * 4;
    pk_store(hpk, DIM, bt, c0,     v.x, v.y);
    pk_store(hpk, DIM, bt, c0 + 2, v.z, v.w);
}

// ---------------- templated packed fp16 GEMM (R12-proven) ------------------
template<int BM, int BN, int WM, int WN>
__global__ void __launch_bounds__(256, 2)
gemm_t(int N, int K,
       const uint4* __restrict__ Apk,
       const uint4* __restrict__ Bpk,
       const float* __restrict__ Res,
       float* __restrict__ C,
       uint32_t* __restrict__ Cpk) {
    constexpr int MT  = BM / 16 / WM;
    constexpr int NT  = BN / 8 / WN;
    constexpr int AW  = BM * 8;
    constexpr int BW  = BN * 8;
    constexpr int STW = AW + BW;
    constexpr int NA  = AW / 256;
    constexpr int NB  = BW / 256;
    extern __shared__ uint4 sm4[];
    const uint32_t sbase = smem_u32(sm4);

    const int tid    = threadIdx.x;
    const int lane   = tid & 31;
    const int wid    = tid >> 5;
    const int warp_m = wid / WN;
    const int warp_n = wid % WN;
    const int g      = lane >> 2;
    const int q      = lane & 3;
    const int row0   = blockIdx.y * BM;
    const int col0   = blockIdx.x * BN;
    const int ktn16  = K >> 4;
    const int kpn    = K >> 5;
    const int ktn    = K >> 6;

    const uint4* asrc[NA]; uint32_t adst[NA];
    const uint4* bsrc[NB]; uint32_t bdst[NB];
#pragma unroll
    for (int i = 0; i < NA; i++) {
        int ca = tid + 256 * i, la = ca & 31, r = ca >> 5;
        int ksl = r & 3, mti = r >> 2;
        asrc[i] = Apk + ((size_t)(row0 / 16 + mti) * ktn16 + ksl) * 32 + la;
        adst[i] = ca;
    }
#pragma unroll
    for (int i = 0; i < NB; i++) {
        int cb = tid + 256 * i, la = cb & 31, r = cb >> 5;
        int kpl = r & 1, nti = r >> 1;
        bsrc[i] = Bpk + ((size_t)(col0 / 8 + nti) * kpn + kpl) * 32 + la;
        bdst[i] = AW + cb;
    }

    float acc[MT][NT][4];
#pragma unroll
    for (int i = 0; i < MT; i++)
#pragma unroll
        for (int j = 0; j < NT; j++)
#pragma unroll
            for (int r = 0; r < 4; r++) acc[i][j][r] = 0.f;

#pragma unroll
    for (int p = 0; p < 2; p++) {
        uint32_t sb = sbase + p * STW * 16;
#pragma unroll
        for (int i = 0; i < NA; i++) cpa16(sb + adst[i] * 16, asrc[i] + p * 128);
#pragma unroll
        for (int i = 0; i < NB; i++) cpa16(sb + bdst[i] * 16, bsrc[i] + p * 64);
        asm volatile("cp.async.commit_group;");
    }

    for (int kt = 0; kt < ktn; kt++) {
        asm volatile("cp.async.wait_group 1;");
        __syncthreads();

        if (kt + 2 < ktn) {
            uint32_t sb = sbase + ((kt + 2) % 3) * STW * 16;
            size_t ao = (size_t)(kt + 2) * 128;
            size_t bo = (size_t)(kt + 2) * 64;
#pragma unroll
            for (int i = 0; i < NA; i++) cpa16(sb + adst[i] * 16, asrc[i] + ao);
#pragma unroll
            for (int i = 0; i < NB; i++) cpa16(sb + bdst[i] * 16, bsrc[i] + bo);
        }
        asm volatile("cp.async.commit_group;");

        const uint4* Ab = sm4 + (kt % 3) * STW;
        const uint4* Bb = Ab + AW;
#pragma unroll
        for (int kp = 0; kp < 2; kp++) {
            uint4 bw[NT];
#pragma unroll
            for (int nt = 0; nt < NT; nt++)
                bw[nt] = Bb[((warp_n * NT + nt) * 2 + kp) * 32 + lane];
#pragma unroll
            for (int hl = 0; hl < 2; hl++) {
                const int ks = kp * 2 + hl;
                uint4 af[MT];
#pragma unroll
                for (int mt = 0; mt < MT; mt++)
                    af[mt] = Ab[((warp_m * MT + mt) * 4 + ks) * 32 + lane];
#pragma unroll
                for (int mt = 0; mt < MT; mt++)
#pragma unroll
                    for (int nt = 0; nt < NT; nt++) {
                        uint32_t b0 = hl ? bw[nt].z : bw[nt].x;
                        uint32_t b1 = hl ? bw[nt].w : bw[nt].y;
                        mma_f16(acc[mt][nt], af[mt].x, af[mt].y, af[mt].z,
                                af[mt].w, b0, b1);
                    }
            }
        }
    }

#pragma unroll
    for (int mt = 0; mt < MT; mt++) {
        int r_lo = row0 + (warp_m * MT + mt) * 16 + g;
#pragma unroll
        for (int nt = 0; nt < NT; nt++) {
            int c = col0 + (warp_n * NT + nt) * 8 + q * 2;
            if (c < N) {
                float2 v0 = make_float2(acc[mt][nt][0], acc[mt][nt][1]);
                float2 v1 = make_float2(acc[mt][nt][2], acc[mt][nt][3]);
                size_t o0 = (size_t)r_lo * N + c;
                size_t o1 = (size_t)(r_lo + 8) * N + c;
                if (Res) {
                    float2 r0v = *(const float2*)(Res + o0);
                    float2 r1v = *(const float2*)(Res + o1);
                    v0.x += r0v.x; v0.y += r0v.y;
                    v1.x += r1v.x; v1.y += r1v.y;
                }
                *(float2*)(C + o0) = v0;
                *(float2*)(C + o1) = v1;
                if (Cpk) {
                    pk_store(Cpk, N, r_lo,     c, v0.x, v0.y);
                    pk_store(Cpk, N, r_lo + 8, c, v1.x, v1.y);
                }
            }
        }
    }
}

// ---------------- causal conv (K=4) + SiLU, channel-per-thread -------------
// 16-step t-tiles (latency-bound at larger tiles).
__global__ void __launch_bounds__(256)
conv_ch_kernel(const float* __restrict__ zx,
               const float* __restrict__ cw,
               const float* __restrict__ cb,
               float* __restrict__ xbc) {
    const int ch = blockIdx.x * 256 + threadIdx.x;
    const int t0 = blockIdx.y * 16;
    const int b  = blockIdx.z;
    float4 w = *(const float4*)(cw + ch * 4);
    float bias = cb[ch];
    const float* src = zx + (size_t)(b * TT) * DINPROJ + DINNER + ch;
    float* dst = xbc + (size_t)(b * TT) * CONVCH + ch;
    float x0 = 0.f, x1 = 0.f, x2 = 0.f;
    if (t0 >= 3) {
        x0 = src[(size_t)(t0 - 3) * DINPROJ];
        x1 = src[(size_t)(t0 - 2) * DINPROJ];
        x2 = src[(size_t)(t0 - 1) * DINPROJ];
    }
#pragma unroll
    for (int t = t0; t < t0 + 16; t++) {
        float x3 = src[(size_t)t * DINPROJ];
        float acc = fmaf(x0, w.x, fmaf(x1, w.y, fmaf(x2, w.z,
                         fmaf(x3, w.w, bias))));
        acc = acc / (1.f + expf(-acc));
        dst[(size_t)t * CONVCH] = acc;
        x0 = x1; x1 = x2; x2 = x3;
    }
}

// ---------------- segmented SSM scan pass 1 (f32x2 packed math) ------------
// CTA per (seg, nh, h, b) => 4*NSEG x NHEADS x BB CTAs. Double-buffered.
#define SCH 16
__global__ void __launch_bounds__(256)
scan_seg_kernel(const float* __restrict__ xbc,
                const float* __restrict__ zx,
                const float* __restrict__ dtb,
                const float* __restrict__ alog,
                const float* __restrict__ Dw,
                float* __restrict__ yp,
                float* __restrict__ acum,
                float* __restrict__ send) {
    __shared__ __align__(16) float Xs [2][SCH][64];
    __shared__ __align__(16) float Bss[2][SCH][32];
    __shared__ __align__(16) float Css[2][SCH][32];
    __shared__ float DTraw[2][SCH];
    __shared__ float As[SCH], Dts[SCH];

    const int tid  = threadIdx.x;
    const int nh   = blockIdx.x & 3;
    const int seg  = blockIdx.x >> 2;
    const int h    = blockIdx.y;
    const int b    = blockIdx.z;
    const int lane = tid & 31;
    const int wid  = tid >> 5;
    const int pl   = lane >> 2;
    const int nq   = lane & 3;
    const int p    = wid * 8 + pl;

    const int xoff = h * 64;
    const int boff = DINNER + nh * 32;
    const int coff = DINNER + DSTATE + nh * 32;

    const uint32_t xs_s = smem_u32(&Xs[0][0][0]);
    const uint32_t bs_s = smem_u32(&Bss[0][0][0]);
    const uint32_t cs_s = smem_u32(&Css[0][0][0]);
    const uint32_t dt_s = smem_u32(&DTraw[0][0]);

    ull s2[4];
#pragma unroll
    for (int i = 0; i < 4; i++) s2[i] = 0ULL;
    const float dtbv = dtb[h];
    const float aexp = expf(alog[h]);
    const float Dh   = (nh == 0) ? Dw[h] : 0.f;
    const float* xrow = xbc + (size_t)b * TT * CONVCH;
    const float* zrow = zx + (size_t)b * TT * DINPROJ;
    float* yout = yp + ((size_t)nh * BT + (size_t)b * TT) * DINNER + h * 64;
    float* acrow = acum + (size_t)(b * NHEADS + h) * TT;
    float carry = 1.f;

    // stage one chunk into buffer `buf`: 512 float4 (X 256, B 128, C 128)
    auto stage = [&](int t0, int buf) {
#pragma unroll
        for (int k = 0; k < 2; k++) {
            int j = tid + 256 * k;
            int tt, q4, choff;
            uint32_t dst;
            if (j < 256) {
                tt = j >> 4; q4 = j & 15;
                choff = xoff + q4 * 4;
                dst = xs_s + (buf * SCH * 64 + tt * 64 + q4 * 4) * 4;
            } else if (j < 384) {
                int jj = j - 256; tt = jj >> 3; q4 = jj & 7;
                choff = boff + q4 * 4;
                int p4 = (((q4 & 1) << 2) + (q4 >> 1)) * 4;
                dst = bs_s + (buf * SCH * 32 + tt * 32 + p4) * 4;
            } else {
                int jj = j - 384; tt = jj >> 3; q4 = jj & 7;
                choff = coff + q4 * 4;
                int p4 = (((q4 & 1) << 2) + (q4 >> 1)) * 4;
                dst = cs_s + (buf * SCH * 32 + tt * 32 + p4) * 4;
            }
            cpa16(dst, xrow + (size_t)(t0 + tt) * CONVCH + choff);
        }
        if (tid < SCH)
            cpa4(dt_s + (buf * SCH + tid) * 4,
                 zrow + (size_t)(t0 + tid) * DINPROJ + (DINNER + CONVCH) + h);
    };

    const int tstart = seg * TSEG;
    stage(tstart, 0);
    asm volatile("cp.async.commit_group;");

    const int nchunks = TSEG / SCH;
    for (int c = 0; c < nchunks; c++) {
        const int buf = c & 1;
        const int t0 = tstart + c * SCH;
        if (c + 1 < nchunks) stage(t0 + SCH, buf ^ 1);
        asm volatile("cp.async.commit_group;");
        asm volatile("cp.async.wait_group 1;");
        __syncthreads();

        if (tid < SCH) {
            float v = DTraw[buf][tid] + dtbv;
            float d = (v > 20.f) ? v : log1pf(expf(v));
            Dts[tid] = d;
            As[tid]  = expf(-aexp * d);
        }
        __syncthreads();

        if (nh == 0 && tid == 0) {
            float cc = carry;
#pragma unroll
            for (int tt = 0; tt < SCH; tt++) {
                cc *= As[tt];
                acrow[t0 + tt] = cc;
            }
            carry = cc;
        }

#pragma unroll
        for (int tt = 0; tt < SCH; tt++) {
            const float da   = As[tt];
            const float xv   = Xs[buf][tt][p];
            const float coef = Dts[tt] * xv;
            const ull da2 = pk2(da, da);
            const ull cf2 = pk2(coef, coef);
            const ulonglong2* B2 = (const ulonglong2*)&Bss[buf][tt][0];
            const ulonglong2* C2 = (const ulonglong2*)&Css[buf][tt][0];
            ull part2 = 0ULL;
#pragma unroll
            for (int i4 = 0; i4 < 2; i4++) {
                ulonglong2 bv = B2[i4 * 4 + nq];
                ulonglong2 cv = C2[i4 * 4 + nq];
                s2[i4 * 2]     = fma2(da2, s2[i4 * 2],     mul2(cf2, bv.x));
                s2[i4 * 2 + 1] = fma2(da2, s2[i4 * 2 + 1], mul2(cf2, bv.y));
                part2 = fma2(s2[i4 * 2],     cv.x, part2);
                part2 = fma2(s2[i4 * 2 + 1], cv.y, part2);
            }
            float plo, phi;
            upk2(part2, plo, phi);
            float part = plo + phi;
            part += __shfl_xor_sync(0xFFFFFFFFu, part, 1);
            part += __shfl_xor_sync(0xFFFFFFFFu, part, 2);
            if (nq == 0)
                yout[(size_t)(t0 + tt) * DINNER + p] = fmaf(Dh, xv, part);
        }
        __syncthreads();
    }

    // ---- write local end state in natural n order ----
    float sf[8];
    upk2(s2[0], sf[0], sf[1]);
    upk2(s2[1], sf[2], sf[3]);
    upk2(s2[2], sf[4], sf[5]);
    upk2(s2[3], sf[6], sf[7]);
#pragma unroll
    for (int i4 = 0; i4 < 2; i4++) {
        int gidx = i4 * 4 + nq;
        int q4   = ((gidx & 3) << 1) | (gidx >> 2);
#pragma unroll
        for (int j = 0; j < 4; j++) {
            int ng = nh * 32 + q4 * 4 + j;
            send[((size_t)((b * NHEADS + h) * NSEG + seg) * 64 + p) * DSTATE +
                 ng] = sf[i4 * 4 + j];
        }
    }
}

// ---------------- pass 2: propagate segment init states (generic NSEG) -----
__global__ void propagate_kernel(const float* __restrict__ send,
                                 const float* __restrict__ acum,
                                 float* __restrict__ sstart) {
    const int h = blockIdx.x, b = blockIdx.y;
    const size_t base = (size_t)(b * NHEADS + h);
    const float* se = send + base * NSEG * 64 * DSTATE;
    float* ss = sstart + base * (NSEG - 1) * 64 * DSTATE;
    const float* ac = acum + base * TT;
    const int SEGSZ = 64 * DSTATE;
    for (int e = threadIdx.x; e < SEGSZ; e += 256) {
        float s = se[e];
        ss[e] = s;
#pragma unroll
        for (int sg = 2; sg < NSEG; sg++) {
            float aT = ac[sg * TSEG - 1];
            s = aT * s + se[(size_t)(sg - 1) * SEGSZ + e];
            ss[(size_t)(sg - 1) * SEGSZ + e] = s;
        }
    }
}

// ---------------- pass 3: correction y += A_cum * (C . S_start) ------------
__global__ void __launch_bounds__(256)
correct_kernel(const float* __restrict__ sstart,
               const float* __restrict__ acum,
               const float* __restrict__ xbc,
               float* __restrict__ yp) {
    extern __shared__ float psm[];
    float* Ssm = psm;                // [n][p] : DSTATE x 64
    float* Csm = psm + DSTATE * 64;  // [tt][n] : 64 x DSTATE
    const int sg  = blockIdx.x;
    const int seg = sg + 1;
    const int h   = blockIdx.y;
    const int b   = blockIdx.z;

    const float* S = sstart +
        ((size_t)(b * NHEADS + h) * (NSEG - 1) + sg) * 64 * DSTATE;
    for (int e = threadIdx.x; e < 64 * DSTATE; e += 256) {
        int p = e >> 7, n = e & 127;
        Ssm[n * 64 + p] = S[e];
    }

    const int p  = threadIdx.x & 63;
    const int tg = threadIdx.x >> 6;
    const float* ac = acum + (size_t)(b * NHEADS + h) * TT + seg * TSEG;

    for (int blk = 0; blk < TSEG / 64; blk++) {
        __syncthreads();
        for (int e = threadIdx.x; e < 64 * DSTATE / 4; e += 256) {
            int tt = e >> 5, n4 = e & 31;
            ((float4*)(Csm + tt * DSTATE))[n4] =
                ((const float4*)(xbc +
                    (size_t)(b * TT + seg * TSEG + blk * 64 + tt) * CONVCH +
                    DINNER + DSTATE))[n4];
        }
        __syncthreads();
#pragma unroll 4
        for (int i = 0; i < 16; i++) {
            int tl = i * 4 + tg;
            int t  = seg * TSEG + blk * 64 + tl;
            float a = ac[blk * 64 + tl];
            const float4* Cr = (const float4*)(Csm + tl * DSTATE);
            float dot = 0.f;
#pragma unroll
            for (int n4 = 0; n4 < 32; n4++) {
                float4 cv = Cr[n4];
                dot = fmaf(cv.x, Ssm[(n4 * 4 + 0) * 64 + p], dot);
                dot = fmaf(cv.y, Ssm[(n4 * 4 + 1) * 64 + p], dot);
                dot = fmaf(cv.z, Ssm[(n4 * 4 + 2) * 64 + p], dot);
                dot = fmaf(cv.w, Ssm[(n4 * 4 + 3) * 64 + p], dot);
            }
            float* yptr = yp + (size_t)(b * TT + t) * DINNER + h * 64 + p;
            *yptr += a * dot;
        }
    }
}

// ---------------- fused gate + RMSNorm + packed write ----------------------
__global__ void __launch_bounds__(256)
rmsgate_kernel(const float* __restrict__ yp,
               const float* __restrict__ zx,
               const float* __restrict__ w,
               uint32_t* __restrict__ ypk) {
    __shared__ float vc[DINNER];
    __shared__ float sh[9];
    const int bt = blockIdx.x;
    const size_t L = (size_t)BT * DINNER;
    const float* r0 = yp + (size_t)bt * DINNER;
    const float* zr = zx + (size_t)bt * DINPROJ;

    float ss = 0.f;
    for (int i = threadIdx.x * 2; i < DINNER; i += 512) {
        float2 a0 = *(const float2*)(r0 + i);
        float2 a1 = *(const float2*)(r0 + L + i);
        float2 a2 = *(const float2*)(r0 + 2 * L + i);
        float2 a3 = *(const float2*)(r0 + 3 * L + i);
        float2 z2 = *(const float2*)(zr + i);
        float y0 = a0.x + a1.x + a2.x + a3.x;
        float y1 = a0.y + a1.y + a2.y + a3.y;
        float v0 = y0 * (z2.x / (1.f + expf(-z2.x)));
        float v1 = y1 * (z2.y / (1.f + expf(-z2.y)));
        vc[i] = v0; vc[i + 1] = v1;
        ss = fmaf(v0, v0, fmaf(v1, v1, ss));
    }
#pragma unroll
    for (int o = 16; o; o >>= 1) ss += __shfl_xor_sync(0xFFFFFFFFu, ss, o);
    int wd = threadIdx.x >> 5, lane = threadIdx.x & 31;
    if (lane == 0) sh[wd] = ss;
    __syncthreads();
    if (wd == 0) {
        float v = (lane < 8) ? sh[lane] : 0.f;
#pragma unroll
        for (int o = 16; o; o >>= 1) v += __shfl_xor_sync(0xFFFFFFFFu, v, o);
        if (lane == 0) sh[8] = rsqrtf(v / DINNER + 1e-5f);
    }
    __syncthreads();
    float sc = sh[8];
    for (int i = threadIdx.x * 2; i < DINNER; i += 512) {
        float o0 = vc[i] * sc * w[i];
        float o1 = vc[i + 1] * sc * w[i + 1];
        pk_store(ypk, DINNER, bt, i, o0, o1);
    }
}

// ---------------- final RMSNorm (+ packed write) ----------------
__global__ void rmsnorm_kernel(float* __restrict__ data,
                               const float* __restrict__ w, int n,
                               uint32_t* __restrict__ pk) {
    float* r = data + (size_t)blockIdx.x * n;
    float ss = 0.f;
    for (int i = threadIdx.x; i < n; i += blockDim.x) {
        float v = r[i];
        ss = fmaf(v, v, ss);
    }
#pragma unroll
    for (int o = 16; o; o >>= 1) ss += __shfl_xor_sync(0xFFFFFFFFu, ss, o);
    __shared__ float sh[9];
    int wd = threadIdx.x >> 5, lane = threadIdx.x & 31;
    if (lane == 0) sh[wd] = ss;
    __syncthreads();
    if (wd == 0) {
        float v = (lane < 8) ? sh[lane] : 0.f;
#pragma unroll
        for (int o = 16; o; o >>= 1) v += __shfl_xor_sync(0xFFFFFFFFu, v, o);
        if (lane == 0) sh[8] = rsqrtf(v / n + 1e-5f);
    }
    __syncthreads();
    float sc = sh[8];
    for (int i = threadIdx.x * 2; i < n; i += 2 * blockDim.x) {
        float o0 = r[i] * sc * w[i];
        float o1 = r[i + 1] * sc * w[i + 1];
        r[i] = o0; r[i + 1] = o1;
        pk_store(pk, n, blockIdx.x, i, o0, o1);
    }
}

// ---------------- launcher ----------------
extern "C" void kernel_launch(void* const* d_in, const int* in_sizes, int n_in,
                              void* d_out, int out_size) {
    const int*   x            = (const int*)  d_in[0];
    const float* embed        = (const float*)d_in[1];
    const float* in_proj_w    = (const float*)d_in[2];
    const float* conv_w       = (const float*)d_in[3];
    const float* conv_b       = (const float*)d_in[4];
    const float* dt_bias      = (const float*)d_in[5];
    const float* A_log        = (const float*)d_in[6];
    const float* Dw           = (const float*)d_in[7];
    const float* gnorm_w      = (const float*)d_in[8];
    const float* out_proj_w   = (const float*)d_in[9];
    const float* final_norm_w = (const float*)d_in[10];
    float* out = (float*)d_out;

    float *ph, *pzx, *pxbc, *pyp, *pac, *pse, *pss;
    uint4 *pwin, *pwout, *pemb, *phpk, *pypk;
    cudaGetSymbolAddress((void**)&ph,    g_h);
    cudaGetSymbolAddress((void**)&pzx,   g_zx);
    cudaGetSymbolAddress((void**)&pxbc,  g_xbc);
    cudaGetSymbolAddress((void**)&pyp,   g_yp);
    cudaGetSymbolAddress((void**)&pac,   g_acum);
    cudaGetSymbolAddress((void**)&pse,   g_send);
    cudaGetSymbolAddress((void**)&pss,   g_sstart);
    cudaGetSymbolAddress((void**)&pwin,  g_win_pk);
    cudaGetSymbolAddress((void**)&pwout, g_wout_pk);
    cudaGetSymbolAddress((void**)&pemb,  g_emb_pk);
    cudaGetSymbolAddress((void**)&phpk,  g_h_pk);
    cudaGetSymbolAddress((void**)&pypk,  g_y_pk);
    uint32_t* phpk32 = (uint32_t*)phpk;
    uint32_t* pypk32 = (uint32_t*)pypk;

    auto gemm_big   = gemm_t<128, 128, 2, 4>;
    auto gemm_nar   = gemm_t<128, 64,  4, 2>;
    auto gemm_small = gemm_t<64,  64,  2, 4>;
    const int SM_BIG = 3 * (128 + 128) * 8 * 16;
    const int SM_NAR = 3 * (128 + 64) * 8 * 16;
    const int SM_SML = 3 * (64 + 64) * 8 * 16;
    const int SM_COR = (DSTATE * 64 + 64 * DSTATE) * 4;
    cudaFuncSetAttribute(gemm_big, cudaFuncAttributeMaxDynamicSharedMemorySize,
                         SM_BIG);
    cudaFuncSetAttribute(gemm_nar, cudaFuncAttributeMaxDynamicSharedMemorySize,
                         SM_NAR);
    cudaFuncSetAttribute(gemm_small, cudaFuncAttributeMaxDynamicSharedMemorySize,
                         SM_SML);
    cudaFuncSetAttribute(correct_kernel,
                         cudaFuncAttributeMaxDynamicSharedMemorySize, SM_COR);

    const int WIN_W  = (NPAD_IN / 8) * (DIM / 32) * 32;
    const int WOUT_W = (DIM / 8) * (DINNER / 32) * 32;
    const int EMB_W  = (VOCAB / 8) * (DIM / 32) * 32;

    embed_kernel<<<BT, 256>>>(x, embed, ph, phpk32);
    pack_b<<<WIN_W / 256, 256>>>(in_proj_w, pwin, DIM, DINPROJ);

    for (int l = 0; l < DEPTH; l++) {
        gemm_big<<<dim3(NPAD_IN / 128, BT / 128), 256, SM_BIG>>>(
            DINPROJ, DIM, phpk, pwin + (size_t)l * WIN_W, nullptr, pzx,
            nullptr);
        conv_ch_kernel<<<dim3(CONVCH / 256, TT / 16, BB), 256>>>(
            pzx, conv_w + (size_t)l * CONVCH * 4, conv_b + (size_t)l * CONVCH,
            pxbc);
        scan_seg_kernel<<<dim3(4 * NSEG, NHEADS, BB), 256>>>(
            pxbc, pzx, dt_bias + l * NHEADS, A_log + l * NHEADS,
            Dw + l * NHEADS, pyp, pac, pse);
        propagate_kernel<<<dim3(NHEADS, BB), 256>>>(pse, pac, pss);
        correct_kernel<<<dim3(NSEG - 1, NHEADS, BB), 256, SM_COR>>>(
            pss, pac, pxbc, pyp);
        pack_b<<<WOUT_W / 256, 256>>>(out_proj_w + (size_t)l * DIM * DINNER,
                                      pwout + (size_t)l * WOUT_W, DINNER, DIM);
        if (l + 1 < DEPTH)
            pack_b<<<WIN_W / 256, 256>>>(
                in_proj_w + (size_t)(l + 1) * DINPROJ * DIM,
                pwin + (size_t)(l + 1) * WIN_W, DIM, DINPROJ);
        rmsgate_kernel<<<BT, 256>>>(pyp, pzx, gnorm_w + (size_t)l * DINNER,
                                    pypk32);
        gemm_nar<<<dim3(DIM / 64, BT / 128), 256, SM_NAR>>>(
            DIM, DINNER, pypk, pwout + (size_t)l * WOUT_W, ph, ph, phpk32);
    }

    rmsnorm_kernel<<<BT, 256>>>(ph, final_norm_w, DIM, phpk32);
    pack_b<<<EMB_W / 256, 256>>>(embed, pemb, DIM, VOCAB);
    gemm_small<<<dim3(VOCAB / 64, BT / 64), 256, SM_SML>>>(
        VOCAB, DIM, phpk, pemb, nullptr, out, nullptr);
}